// round 10
// baseline (speedup 1.0000x reference)
#include <cuda_runtime.h>
#include <cuda_fp16.h>
#include <cstddef>

#define U_N 50000
#define I_N 100000
#define E_N 1600000
#define B_N 16384
#define N_ALL (U_N + I_N)          // 150000 combined nodes
#define SCAN_BLK 8192              // elems per scan block (1024 thr x 8)
#define SCAN_NB ((N_ALL + SCAN_BLK - 1) / SCAN_BLK)   // 19
#define HSTRIDE 80                 // half row: 64 half feats + 8 fp32 scores (160B)

// ---------------- fp32 scratch (stride-64 feature rows) ----------------
constexpr size_t F1U = 0;                              // layer-1 gemm out (self)
constexpr size_t F1I = F1U + (size_t)U_N * 64;
constexpr size_t H1U = F1I + (size_t)I_N * 64;         // agg1 out = gemm-l2 in
constexpr size_t H1I = H1U + (size_t)U_N * 64;
constexpr size_t F2U = H1I + (size_t)I_N * 64;         // layer-2 gemm out (self)
constexpr size_t F2I = F2U + (size_t)U_N * 64;
constexpr size_t UF_ = F2I + (size_t)I_N * 64;         // agg2 out (final feats)
constexpr size_t IF_ = UF_ + (size_t)U_N * 64;
constexpr size_t WORK_FLOATS = IF_ + (size_t)I_N * 64;

// ---------------- fp16 peer rows (feats half + scores fp32) ----------------
constexpr size_t HP1U = 0;
constexpr size_t HP1I = HP1U + (size_t)U_N * HSTRIDE;
constexpr size_t HP2U = HP1I + (size_t)I_N * HSTRIDE;
constexpr size_t HP2I = HP2U + (size_t)U_N * HSTRIDE;
constexpr size_t HALF_TOTAL = HP2I + (size_t)I_N * HSTRIDE;

// ---------------- int scratch ----------------
constexpr size_t CNT_A = 0;            // 150000 (users then items)  } zeroed
constexpr size_t FLG_U = 150000;       // 50000                      }
constexpr size_t FLG_I = 200000;       // 100000                     }
constexpr size_t ZERO_INTS = 300000;
constexpr size_t OFF_A = 300000;       // 150001 combined exclusive offsets
constexpr size_t CUR_A = 450112;       // 150000
constexpr size_t BSUM  = 600128;       // 32 block sums
constexpr size_t LST   = 600192;       // 2E combined edge lists
constexpr size_t IDX_INTS = LST + 2 * (size_t)E_N;

__device__ __align__(16) float  g_work[WORK_FLOATS];
__device__ __align__(16) __half g_half[HALF_TOTAL];
__device__ __align__(16) int    g_idx[IDX_INTS];

__device__ __forceinline__ float elu1(float x) {
    return x > 0.f ? x : expm1f(x);
}

// ---------------- CSR build ----------------
__global__ void hist_k(const int* __restrict__ eu, const int* __restrict__ ei)
{
    int t = blockIdx.x * 256 + threadIdx.x;
    if (t >= E_N / 4) return;
#pragma unroll
    for (int k = 0; k < 4; k++) {
        int e = t + k * (E_N / 4);
        atomicAdd(&g_idx[CNT_A + __ldg(eu + e)], 1);
        atomicAdd(&g_idx[CNT_A + U_N + __ldg(ei + e)], 1);
    }
}

// ---- 3-phase multi-block exclusive scan over the combined counts ----
__global__ void scanA_k(const int* __restrict__ cnt, int* __restrict__ off,
                        int* __restrict__ bsum)
{
    __shared__ int wsum[32];
    int tid = threadIdx.x;
    int lane = tid & 31, warp = tid >> 5;
    int base = blockIdx.x * SCAN_BLK + tid * 8;
    int v[8];
    int s = 0;
#pragma unroll
    for (int k = 0; k < 8; k++) {
        v[k] = (base + k < N_ALL) ? cnt[base + k] : 0;
        s += v[k];
    }
    int x = s;
#pragma unroll
    for (int d = 1; d < 32; d <<= 1) {
        int t = __shfl_up_sync(0xffffffffu, x, d);
        if (lane >= d) x += t;
    }
    if (lane == 31) wsum[warp] = x;
    __syncthreads();
    if (tid < 32) {
        int w = wsum[tid];
#pragma unroll
        for (int d = 1; d < 32; d <<= 1) {
            int t = __shfl_up_sync(0xffffffffu, w, d);
            if (tid >= d) w += t;
        }
        wsum[tid] = w;
    }
    __syncthreads();
    int excl = (warp ? wsum[warp - 1] : 0) + x - s;
#pragma unroll
    for (int k = 0; k < 8; k++) {
        if (base + k < N_ALL) off[base + k] = excl;
        excl += v[k];
    }
    if (tid == 0) bsum[blockIdx.x] = wsum[31];
}

__global__ void scanB_k(int* __restrict__ bsum)
{
    int tid = threadIdx.x;   // one warp
    int v = (tid < SCAN_NB) ? bsum[tid] : 0;
    int x = v;
#pragma unroll
    for (int d = 1; d < 32; d <<= 1) {
        int t = __shfl_up_sync(0xffffffffu, x, d);
        if (tid >= d) x += t;
    }
    if (tid < SCAN_NB) bsum[tid] = x - v;   // exclusive
}

__global__ void scanC_k(int* __restrict__ off, int* __restrict__ cur,
                        const int* __restrict__ bsum)
{
    int i = blockIdx.x * 1024 + threadIdx.x;
    if (i >= N_ALL) return;
    int o = off[i] + __ldg(bsum + (i / SCAN_BLK));
    off[i] = o;
    cur[i] = o;
    if (i == 0) off[N_ALL] = 2 * E_N;   // known total
}

__global__ void scat_k(const int* __restrict__ eu, const int* __restrict__ ei)
{
    int t = blockIdx.x * 256 + threadIdx.x;
    if (t >= E_N / 4) return;
#pragma unroll
    for (int k = 0; k < 4; k++) {
        int e = t + k * (E_N / 4);
        int u = __ldg(eu + e), i = __ldg(ei + e);
        int pu = atomicAdd(&g_idx[CUR_A + u], 1);
        g_idx[LST + pu] = i;
        int pi = atomicAdd(&g_idx[CUR_A + U_N + i], 1);
        g_idx[LST + pi] = u;
    }
}

// mark nodes actually consumed by the final dot
__global__ void mark_k(const int* __restrict__ uIdx, const int* __restrict__ iIdx)
{
    int t = blockIdx.x * 256 + threadIdx.x;
    if (t >= B_N) return;
    g_idx[FLG_U + uIdx[t]] = 1;
    g_idx[FLG_I + iIdx[t]] = 1;
}

// ---------------- layer-1 GEMM: [n,64] @ [8][64][8] + head scores ----------------
// Writes fp32 row (stride 64) + fp16 peer row (stride 80 halves, scores fp32)
__global__ void gemm_l1(const float* __restrict__ X,
                        const float* __restrict__ W,   // [8][64][8]
                        const float* __restrict__ a,   // [8][16]
                        int aoff,
                        float* __restrict__ Y, __half* __restrict__ YH, int n)
{
    __shared__ float Ws[64 * 64];
    __shared__ float Es[16 * 64];
    int tid = threadIdx.x;
#pragma unroll
    for (int k = 0; k < 16; k++) {
        int idx = tid + k * 256;
        int d = idx >> 6, c = idx & 63;
        Ws[idx] = W[(c >> 3) * 512 + d * 8 + (c & 7)];
    }
    int q = tid & 15;
    int tr = tid >> 4;
    const float4* Ws4 = (const float4*)Ws;
#pragma unroll
    for (int it = 0; it < 4; it++) {
        size_t r0 = ((size_t)blockIdx.x * 4 + it) * 16;
        if (r0 >= (size_t)n) return;
        __syncthreads();
        ((float4*)Es)[tid] = *(const float4*)(X + (r0 + tr) * 64 + q * 4);
        __syncthreads();
        float4 acc = make_float4(0.f, 0.f, 0.f, 0.f);
#pragma unroll
        for (int d = 0; d < 64; d++) {
            float e = Es[tr * 64 + d];
            float4 w = Ws4[d * 16 + q];
            acc.x += e * w.x; acc.y += e * w.y; acc.z += e * w.z; acc.w += e * w.w;
        }
        size_t r = r0 + tr;
        ((float4*)(Y + r * 64))[q] = acc;
        __half* hr = YH + r * HSTRIDE;
        ((__half2*)hr)[2 * q]     = __floats2half2_rn(acc.x, acc.y);
        ((__half2*)hr)[2 * q + 1] = __floats2half2_rn(acc.z, acc.w);
        int h = q >> 1;
        const float* ap = a + h * 16 + aoff + (q & 1) * 4;
        float p = acc.x * ap[0] + acc.y * ap[1] + acc.z * ap[2] + acc.w * ap[3];
        p += __shfl_xor_sync(0xffffffffu, p, 1);
        if ((q & 1) == 0) ((float*)(hr + 64))[h] = p;
    }
}

// ---------------- layer-2 GEMM: [n,64]@[64,64] + scalar score ----------------
__global__ void gemm_l2(const float* __restrict__ X,   // stride 64
                        const float* __restrict__ W,   // [64][64]
                        const float* __restrict__ a,   // [128]
                        int aoff,
                        float* __restrict__ Y, __half* __restrict__ YH, int n)
{
    __shared__ float Ws[64 * 64];
    __shared__ float Es[16 * 64];
    int tid = threadIdx.x;
#pragma unroll
    for (int k = 0; k < 4; k++)
        ((float4*)Ws)[tid + k * 256] = ((const float4*)W)[tid + k * 256];
    int q = tid & 15;
    int tr = tid >> 4;
    const float4* Ws4 = (const float4*)Ws;
#pragma unroll
    for (int it = 0; it < 4; it++) {
        size_t r0 = ((size_t)blockIdx.x * 4 + it) * 16;
        if (r0 >= (size_t)n) return;
        __syncthreads();
        ((float4*)Es)[tid] = *(const float4*)(X + (r0 + tr) * 64 + q * 4);
        __syncthreads();
        float4 acc = make_float4(0.f, 0.f, 0.f, 0.f);
#pragma unroll
        for (int k = 0; k < 64; k++) {
            float e = Es[tr * 64 + k];
            float4 w = Ws4[k * 16 + q];
            acc.x += e * w.x; acc.y += e * w.y; acc.z += e * w.z; acc.w += e * w.w;
        }
        size_t r = r0 + tr;
        ((float4*)(Y + r * 64))[q] = acc;
        __half* hr = YH + r * HSTRIDE;
        ((__half2*)hr)[2 * q]     = __floats2half2_rn(acc.x, acc.y);
        ((__half2*)hr)[2 * q + 1] = __floats2half2_rn(acc.z, acc.w);
        const float* ap = a + aoff + q * 4;
        float p = acc.x * ap[0] + acc.y * ap[1] + acc.z * ap[2] + acc.w * ap[3];
#pragma unroll
        for (int k = 1; k < 16; k <<= 1)
            p += __shfl_xor_sync(0xffffffffu, p, k, 16);
        if (q == 0) *((float*)(hr + 64)) = p;
    }
}

// ---------------- CSR aggregation + normalize + elu (fused epilogue) ----------
// Peer gathers hit the compact fp16 rows (160B); scores stay fp32-exact.
// Two-phase: A) parallel score loads + e compute; B) unrolled accumulation via shfl.
// L=1: 8 heads (lane accumulates cols 2l,2l+1; head = lane>>2)
// L=2: scalar score; FLAG filters nodes not consumed downstream.
template<int L, bool FILTER>
__global__ void agg_k(const float* __restrict__ SELF, const __half* __restrict__ SELFH,
                      const __half* __restrict__ PEERH,
                      const int* __restrict__ off, const int* __restrict__ lst,
                      const int* __restrict__ flag,
                      float* __restrict__ OUT, int n)
{
    int node = blockIdx.x * 8 + (threadIdx.x >> 5);
    if (node >= n) return;
    if (FILTER && !__ldg(flag + node)) return;
    int lane = threadIdx.x & 31;
    const __half* selfh = SELFH + (size_t)node * HSTRIDE;
    float sA = (L == 1) ? __ldg((const float*)(selfh + 64) + (lane & 7))
                        : __ldg((const float*)(selfh + 64));
    int o0 = __ldg(off + node), o1 = __ldg(off + node + 1);
    float2 acc = make_float2(0.f, 0.f);
    float rsum = 0.f;

    for (int base = o0; base < o1; base += 32) {
        int rem = o1 - base;                       // >0
        int idx = (lane < rem) ? __ldg(lst + base + lane) : 0;

        float epack[L == 1 ? 8 : 1];
        if (L == 1) {
            // subchunk s: edges s*4..s*4+3; lane handles edge s*4+(lane>>3), head lane&7
#pragma unroll
            for (int s = 0; s < 8; s++) {
                int j = s * 4 + (lane >> 3);
                int p = __shfl_sync(0xffffffffu, idx, j);
                const float* ps = (const float*)(PEERH + (size_t)p * HSTRIDE + 64);
                float sp = (j < rem) ? __ldg(ps + (lane & 7)) : 0.f;
                float x = sA + sp;
                float lx = x >= 0.f ? x : 0.2f * x;
                epack[s] = (j < rem) ? __expf(-lx) : 0.f;
            }
        } else {
            const float* ps = (const float*)(PEERH + (size_t)idx * HSTRIDE + 64);
            float sp = (lane < rem) ? __ldg(ps) : 0.f;
            float x = sA + sp;
            float lx = x >= 0.f ? x : 0.2f * x;
            epack[0] = (lane < rem) ? __expf(-lx) : 0.f;
        }

#pragma unroll
        for (int j = 0; j < 32; j++) {
            int p = __shfl_sync(0xffffffffu, idx, j);
            float eh = (L == 1)
                ? __shfl_sync(0xffffffffu, epack[j >> 2], (j & 3) * 8 + (lane >> 2))
                : __shfl_sync(0xffffffffu, epack[0], j);
            if (j < rem) {
                __half2 hv = __ldg((const __half2*)(PEERH + (size_t)p * HSTRIDE) + lane);
                float2 f = __half22float2(hv);
                acc.x += eh * f.x;
                acc.y += eh * f.y;
                rsum += eh;
            }
        }
    }
    // lane's rsum == rowsum for its head (L=1) / the rowsum (L=2)
    float inv = (rsum > 0.f) ? 1.f / rsum : 0.f;
    float2 sf = *(const float2*)(SELF + (size_t)node * 64 + 2 * lane);
    float2 o;
    o.x = elu1(sf.x + acc.x * inv);
    o.y = elu1(sf.y + acc.y * inv);
    *(float2*)(OUT + (size_t)node * 64 + 2 * lane) = o;
}

// ---------------- final: gather rows, dot ----------------
__global__ void final_k(const int* __restrict__ uIdx, const int* __restrict__ iIdx,
                        float* __restrict__ out)
{
    int b = blockIdx.x * 8 + (threadIdx.x >> 5);
    if (b >= B_N) return;
    int lane = threadIdx.x & 31;
    int u = uIdx[b], i = iIdx[b];
    const float* uf = g_work + UF_ + (size_t)u * 64;
    const float* if_ = g_work + IF_ + (size_t)i * 64;
    float acc = uf[lane] * if_[lane] + uf[lane + 32] * if_[lane + 32];
#pragma unroll
    for (int k = 16; k >= 1; k >>= 1)
        acc += __shfl_xor_sync(0xffffffffu, acc, k);
    if (lane == 0) out[b] = acc;
}

// ---------------- launch ----------------
extern "C" void kernel_launch(void* const* d_in, const int* in_sizes, int n_in,
                              void* d_out, int out_size)
{
    const int*   userIdx = (const int*)d_in[0];
    const int*   itemIdx = (const int*)d_in[1];
    const int*   edge_u  = (const int*)d_in[2];
    const int*   edge_i  = (const int*)d_in[3];
    const float* uEmbd   = (const float*)d_in[4];
    const float* iEmbd   = (const float*)d_in[5];
    const float* Wu_h    = (const float*)d_in[6];
    const float* Wi_h    = (const float*)d_in[7];
    const float* a_h     = (const float*)d_in[8];
    const float* Wu_out  = (const float*)d_in[9];
    const float* Wi_out  = (const float*)d_in[10];
    const float* a_out   = (const float*)d_in[11];
    float* out = (float*)d_out;

    void *wp = nullptr, *hp = nullptr, *ip = nullptr;
    cudaGetSymbolAddress(&wp, g_work);
    cudaGetSymbolAddress(&hp, g_half);
    cudaGetSymbolAddress(&ip, g_idx);
    float*  W = (float*)wp;
    __half* Hh = (__half*)hp;
    int*    X = (int*)ip;

    // --- CSR build (combined U+I scan, single contiguous edge list) ---
    cudaMemsetAsync(X + CNT_A, 0, ZERO_INTS * sizeof(int), 0);
    hist_k<<<(E_N / 4 + 255) / 256, 256>>>(edge_u, edge_i);
    mark_k<<<(B_N + 255) / 256, 256>>>(userIdx, itemIdx);
    scanA_k<<<SCAN_NB, 1024>>>(X + CNT_A, X + OFF_A, X + BSUM);
    scanB_k<<<1, 32>>>(X + BSUM);
    scanC_k<<<(N_ALL + 1023) / 1024, 1024>>>(X + OFF_A, X + CUR_A, X + BSUM);
    scat_k<<<(E_N / 4 + 255) / 256, 256>>>(edge_u, edge_i);

    // --- layer 1 transforms ---
    gemm_l1<<<(U_N + 63) / 64, 256>>>(uEmbd, Wu_h, a_h, 0, W + F1U, Hh + HP1U, U_N);
    gemm_l1<<<(I_N + 63) / 64, 256>>>(iEmbd, Wi_h, a_h, 8, W + F1I, Hh + HP1I, I_N);

    // --- layer 1 aggregation (fused normalize + elu) ---
    agg_k<1, false><<<(U_N + 7) / 8, 256>>>(W + F1U, Hh + HP1U, Hh + HP1I,
                                            X + OFF_A, X + LST, nullptr, W + H1U, U_N);
    agg_k<1, false><<<(I_N + 7) / 8, 256>>>(W + F1I, Hh + HP1I, Hh + HP1U,
                                            X + OFF_A + U_N, X + LST, nullptr, W + H1I, I_N);

    // --- layer 2 transforms ---
    gemm_l2<<<(U_N + 63) / 64, 256>>>(W + H1U, Wu_out, a_out, 0,  W + F2U, Hh + HP2U, U_N);
    gemm_l2<<<(I_N + 63) / 64, 256>>>(W + H1I, Wi_out, a_out, 64, W + F2I, Hh + HP2I, I_N);

    // --- layer 2 aggregation (only nodes the final dot consumes) ---
    agg_k<2, true><<<(U_N + 7) / 8, 256>>>(W + F2U, Hh + HP2U, Hh + HP2I,
                                           X + OFF_A, X + LST, X + FLG_U, W + UF_, U_N);
    agg_k<2, true><<<(I_N + 7) / 8, 256>>>(W + F2I, Hh + HP2I, Hh + HP2U,
                                           X + OFF_A + U_N, X + LST, X + FLG_I, W + IF_, I_N);

    // --- final gather + dot ---
    final_k<<<(B_N + 7) / 8, 256>>>(userIdx, itemIdx, out);
}